// round 4
// baseline (speedup 1.0000x reference)
#include <cuda_runtime.h>

#define E_DIM 1024
#define SEQ   2048
#define NH    16
#define HD    64
#define MTOK  4096
#define ATT_SCALE 0.125f
#define XN ((size_t)MTOK * E_DIM)
#define WN ((size_t)E_DIM * E_DIM)

__device__ float g_q[XN];
__device__ float g_k[XN];
__device__ float g_v[XN];
__device__ float g_ctx[XN];
__device__ float g_x[XN];
__device__ float g_wq[WN];
__device__ float g_wk[WN];
__device__ float g_wv[WN];
__device__ float g_wo[WN];

__device__ __forceinline__ unsigned f2tf(float x) {
    unsigned r;
    asm("cvt.rna.tf32.f32 %0, %1;" : "=r"(r) : "f"(x));
    return r;
}
__device__ __forceinline__ float f2tff(float x) {
    return __uint_as_float(f2tf(x));
}

__device__ __forceinline__ void mma_tf32(float* c, const unsigned* a,
                                         unsigned b0, unsigned b1) {
    asm volatile(
        "mma.sync.aligned.m16n8k8.row.col.f32.tf32.tf32.f32 "
        "{%0,%1,%2,%3}, {%4,%5,%6,%7}, {%8,%9}, {%0,%1,%2,%3};\n"
        : "+f"(c[0]), "+f"(c[1]), "+f"(c[2]), "+f"(c[3])
        : "r"(a[0]), "r"(a[1]), "r"(a[2]), "r"(a[3]), "r"(b0), "r"(b1));
}

__device__ __forceinline__ unsigned sptr(const void* p) {
    return (unsigned)__cvta_generic_to_shared(p);
}
__device__ __forceinline__ void cp16(unsigned d, const float* s) {
    asm volatile("cp.async.cg.shared.global [%0], [%1], 16;\n"
                 :: "r"(d), "l"(s));
}
__device__ __forceinline__ void cp_commit() {
    asm volatile("cp.async.commit_group;\n");
}
template <int N>
__device__ __forceinline__ void cp_wait() {
    asm volatile("cp.async.wait_group %0;\n" :: "n"(N));
}

// ---------------------------------------------------------------------------
// Prep: round x + 4 weight matrices to rn-tf32 once.
// ---------------------------------------------------------------------------
__global__ void __launch_bounds__(256)
k_prep(const float* __restrict__ x,
       const float* __restrict__ wq, const float* __restrict__ wk,
       const float* __restrict__ wv, const float* __restrict__ wo)
{
    size_t i = ((size_t)blockIdx.x * 256 + threadIdx.x) * 4;
    const float* s; float* d; size_t off;
    if (i < XN)               { s = x;  d = g_x;  off = i; }
    else if (i < XN + WN)     { s = wq; d = g_wq; off = i - XN; }
    else if (i < XN + 2 * WN) { s = wk; d = g_wk; off = i - XN - 2 * WN + WN; }
    else if (i < XN + 3 * WN) { s = wv; d = g_wv; off = i - XN - 2 * WN; }
    else                      { s = wo; d = g_wo; off = i - XN - 3 * WN; }
    float4 v = *(const float4*)(s + off);
    float4 o = make_float4(f2tff(v.x), f2tff(v.y), f2tff(v.z), f2tff(v.w));
    *(float4*)(d + off) = o;
}

// ---------------------------------------------------------------------------
// tf32 GEMM: C[M,N] = A[M,K] * W[N,K]^T + bias.  Tile 128x128x32, 256 thr,
// 2-stage cp.async pipeline. 8 warps (4x2): warp = 32 rows x 64 cols.
// ---------------------------------------------------------------------------
#define KC   32
#define AST  36                 // smem row stride (floats)
#define GSTG (128 * AST)        // one array, one stage (unsigned count)

template <bool RND>
__device__ __forceinline__ void gemm_body(const float* __restrict__ A,
                                          const float* __restrict__ W,
                                          const float* __restrict__ bias,
                                          float* __restrict__ C,
                                          unsigned* sm)
{
    const int tid  = threadIdx.x;
    const int lane = tid & 31, warp = tid >> 5;
    const int g = lane >> 2, tig = lane & 3;
    const int m0 = (warp >> 1) * 32;
    const int n0 = (warp & 1) * 64;
    const int row0 = blockIdx.y * 128;
    const int col0 = blockIdx.x * 128;

    const int lrow = tid >> 1;
    const int lcb  = (tid & 1) * 16;
    const float* Ag = A + (size_t)(row0 + lrow) * E_DIM + lcb;
    const float* Wg = W + (size_t)(col0 + lrow) * E_DIM + lcb;

    float acc[2][8][4];
#pragma unroll
    for (int mi = 0; mi < 2; mi++)
#pragma unroll
        for (int ni = 0; ni < 8; ni++)
#pragma unroll
            for (int j = 0; j < 4; j++) acc[mi][ni][j] = 0.f;

    const unsigned dA0 = sptr(sm + lrow * AST + lcb);
    const unsigned dW0 = dA0 + GSTG * 4;

    // prologue: stage 0
#pragma unroll
    for (int j = 0; j < 4; j++) {
        cp16(dA0 + 16 * j, Ag + 4 * j);
        cp16(dW0 + 16 * j, Wg + 4 * j);
    }
    cp_commit();

    const int NKT = E_DIM / KC;
    for (int kt = 0; kt < NKT; kt++) {
        if (kt + 1 < NKT) {
            const unsigned dd = ((kt + 1) & 1) * 2 * GSTG * 4;
            const int ko = (kt + 1) * KC;
#pragma unroll
            for (int j = 0; j < 4; j++) {
                cp16(dA0 + dd + 16 * j, Ag + ko + 4 * j);
                cp16(dW0 + dd + 16 * j, Wg + ko + 4 * j);
            }
            cp_commit();
            cp_wait<1>();
        } else {
            cp_wait<0>();
        }
        __syncthreads();

        const unsigned* As = sm + (kt & 1) * 2 * GSTG;
        const unsigned* Ws = As + GSTG;
#pragma unroll
        for (int kk = 0; kk < KC; kk += 8) {
            unsigned a[2][4], bf[8][2];
#pragma unroll
            for (int mi = 0; mi < 2; mi++) {
                const int row = m0 + mi * 16;
                a[mi][0] = As[(row + g) * AST + kk + tig];
                a[mi][1] = As[(row + g + 8) * AST + kk + tig];
                a[mi][2] = As[(row + g) * AST + kk + tig + 4];
                a[mi][3] = As[(row + g + 8) * AST + kk + tig + 4];
            }
#pragma unroll
            for (int ni = 0; ni < 8; ni++) {
                const int col = n0 + ni * 8;
                bf[ni][0] = Ws[(col + g) * AST + kk + tig];
                bf[ni][1] = Ws[(col + g) * AST + kk + tig + 4];
            }
#pragma unroll
            for (int mi = 0; mi < 2; mi++)
#pragma unroll
                for (int ni = 0; ni < 8; ni++)
                    mma_tf32(acc[mi][ni], a[mi], bf[ni][0], bf[ni][1]);
        }
        __syncthreads();
    }

#pragma unroll
    for (int mi = 0; mi < 2; mi++) {
#pragma unroll
        for (int ni = 0; ni < 8; ni++) {
            const int row = row0 + m0 + mi * 16;
            const int col = col0 + n0 + ni * 8 + 2 * tig;
            const float bx = bias[col], by = bias[col + 1];
            float2 r0, r1;
            if (RND) {
                r0 = make_float2(f2tff(acc[mi][ni][0] + bx), f2tff(acc[mi][ni][1] + by));
                r1 = make_float2(f2tff(acc[mi][ni][2] + bx), f2tff(acc[mi][ni][3] + by));
            } else {
                r0 = make_float2(acc[mi][ni][0] + bx, acc[mi][ni][1] + by);
                r1 = make_float2(acc[mi][ni][2] + bx, acc[mi][ni][3] + by);
            }
            *(float2*)&C[(size_t)(row + g) * E_DIM + col] = r0;
            *(float2*)&C[(size_t)(row + g + 8) * E_DIM + col] = r1;
        }
    }
}

__global__ void __launch_bounds__(256)
k_gemm_qkv(const float* __restrict__ bq, const float* __restrict__ bk,
           const float* __restrict__ bv)
{
    extern __shared__ unsigned dynsm[];
    const float *W, *bias;
    float* C;
    if (blockIdx.z == 0)      { W = g_wq; bias = bq; C = g_q; }
    else if (blockIdx.z == 1) { W = g_wk; bias = bk; C = g_k; }
    else                      { W = g_wv; bias = bv; C = g_v; }
    gemm_body<true>(g_x, W, bias, C, dynsm);
}

__global__ void __launch_bounds__(256)
k_gemm_out(const float* __restrict__ bo, float* __restrict__ Cout)
{
    extern __shared__ unsigned dynsm[];
    gemm_body<false>(g_ctx, g_wo, bo, Cout, dynsm);
}

// ---------------------------------------------------------------------------
// Flash attention tf32, 2-stage cp.async on K/V. CTA = (b,h,64-q tile),
// 128 thr = 4 warps, warp owns 16 query rows.
// ---------------------------------------------------------------------------
#define FS    68
#define FSTG  (2 * 64 * FS)     // K + V, one stage (unsigned count)

__global__ void __launch_bounds__(128) k_flash()
{
    extern __shared__ unsigned sm[];
    unsigned* Ps = sm + 2 * FSTG;   // 64 x FS (Q staging, then P)

    const int tid  = threadIdx.x;
    const int lane = tid & 31, warp = tid >> 5;
    const int g = lane >> 2, tig = lane & 3;
    const int qt = blockIdx.x, h = blockIdx.y, b = blockIdx.z;
    const size_t base = (size_t)b * SEQ * E_DIM + (size_t)h * HD;
    const int wr = warp * 16;

    const int lrow = tid >> 1;           // 0..63
    const int lcb  = (tid & 1) * 32;     // 0 or 32
    const float* Kg = g_k + base + (size_t)lrow * E_DIM + lcb;
    const float* Vg = g_v + base + (size_t)lrow * E_DIM + lcb;
    const unsigned dK0 = sptr(sm + lrow * FS + lcb);
    const unsigned dV0 = dK0 + 64 * FS * 4;

    // prologue: stage 0 = kt 0
#pragma unroll
    for (int j = 0; j < 8; j++) {
        cp16(dK0 + 16 * j, Kg + 4 * j);
        cp16(dV0 + 16 * j, Vg + 4 * j);
    }
    cp_commit();

    // stage Q (64x64, already tf32-rounded) into Ps
    for (int i = tid; i < 64 * 16; i += 128) {
        const int rr = i >> 4, c4 = (i & 15) << 2;
        *(float4*)&Ps[rr * FS + c4] =
            *(const float4*)&g_q[base + (size_t)(qt * 64 + rr) * E_DIM + c4];
    }
    __syncthreads();

    unsigned qa[8][4];
#pragma unroll
    for (int ks = 0; ks < 8; ks++) {
        qa[ks][0] = Ps[(wr + g) * FS + 8 * ks + tig];
        qa[ks][1] = Ps[(wr + g + 8) * FS + 8 * ks + tig];
        qa[ks][2] = Ps[(wr + g) * FS + 8 * ks + tig + 4];
        qa[ks][3] = Ps[(wr + g + 8) * FS + 8 * ks + tig + 4];
    }
    __syncthreads();

    float o[8][4];
#pragma unroll
    for (int ni = 0; ni < 8; ni++)
#pragma unroll
        for (int j = 0; j < 4; j++) o[ni][j] = 0.f;
    float m0 = -3.0e38f, m1 = -3.0e38f, l0 = 0.f, l1 = 0.f;

    const int NT = SEQ / 64;
    for (int kt = 0; kt < NT; kt++) {
        if (kt + 1 < NT) {
            const unsigned dd = ((kt + 1) & 1) * FSTG * 4;
            const size_t go = (size_t)(kt + 1) * 64 * E_DIM;
#pragma unroll
            for (int j = 0; j < 8; j++) {
                cp16(dK0 + dd + 16 * j, Kg + go + 4 * j);
                cp16(dV0 + dd + 16 * j, Vg + go + 4 * j);
            }
            cp_commit();
            cp_wait<1>();
        } else {
            cp_wait<0>();
        }
        __syncthreads();

        const unsigned* Ks = sm + (kt & 1) * FSTG;
        const unsigned* Vs = Ks + 64 * FS;

        // S = Q K^T
        float s[8][4];
#pragma unroll
        for (int ni = 0; ni < 8; ni++)
#pragma unroll
            for (int j = 0; j < 4; j++) s[ni][j] = 0.f;
#pragma unroll
        for (int ks = 0; ks < 8; ks++) {
#pragma unroll
            for (int ni = 0; ni < 8; ni++) {
                unsigned b0 = Ks[(8 * ni + g) * FS + 8 * ks + tig];
                unsigned b1 = Ks[(8 * ni + g) * FS + 8 * ks + tig + 4];
                mma_tf32(s[ni], qa[ks], b0, b1);
            }
        }

        // online softmax
        float mx0 = -3.0e38f, mx1 = -3.0e38f;
#pragma unroll
        for (int ni = 0; ni < 8; ni++) {
            s[ni][0] *= ATT_SCALE; s[ni][1] *= ATT_SCALE;
            s[ni][2] *= ATT_SCALE; s[ni][3] *= ATT_SCALE;
            mx0 = fmaxf(mx0, fmaxf(s[ni][0], s[ni][1]));
            mx1 = fmaxf(mx1, fmaxf(s[ni][2], s[ni][3]));
        }
        mx0 = fmaxf(mx0, __shfl_xor_sync(0xffffffffu, mx0, 1));
        mx0 = fmaxf(mx0, __shfl_xor_sync(0xffffffffu, mx0, 2));
        mx1 = fmaxf(mx1, __shfl_xor_sync(0xffffffffu, mx1, 1));
        mx1 = fmaxf(mx1, __shfl_xor_sync(0xffffffffu, mx1, 2));
        const float mn0 = fmaxf(m0, mx0), mn1 = fmaxf(m1, mx1);
        const float al0 = __expf(m0 - mn0), al1 = __expf(m1 - mn1);
        float s0 = 0.f, s1 = 0.f;
#pragma unroll
        for (int ni = 0; ni < 8; ni++) {
            float p0 = __expf(s[ni][0] - mn0);
            float p1 = __expf(s[ni][1] - mn0);
            float p2 = __expf(s[ni][2] - mn1);
            float p3 = __expf(s[ni][3] - mn1);
            s0 += p0 + p1; s1 += p2 + p3;
            uint2 w0 = make_uint2(f2tf(p0), f2tf(p1));
            uint2 w1 = make_uint2(f2tf(p2), f2tf(p3));
            *(uint2*)&Ps[(wr + g) * FS + 8 * ni + 2 * tig] = w0;
            *(uint2*)&Ps[(wr + g + 8) * FS + 8 * ni + 2 * tig] = w1;
        }
        s0 += __shfl_xor_sync(0xffffffffu, s0, 1);
        s0 += __shfl_xor_sync(0xffffffffu, s0, 2);
        s1 += __shfl_xor_sync(0xffffffffu, s1, 1);
        s1 += __shfl_xor_sync(0xffffffffu, s1, 2);
        l0 = l0 * al0 + s0;
        l1 = l1 * al1 + s1;
        m0 = mn0; m1 = mn1;
#pragma unroll
        for (int ni = 0; ni < 8; ni++) {
            o[ni][0] *= al0; o[ni][1] *= al0;
            o[ni][2] *= al1; o[ni][3] *= al1;
        }
        __syncwarp();

        // O += P V
#pragma unroll
        for (int ks = 0; ks < 8; ks++) {
            unsigned pa[4];
            pa[0] = Ps[(wr + g) * FS + 8 * ks + tig];
            pa[1] = Ps[(wr + g + 8) * FS + 8 * ks + tig];
            pa[2] = Ps[(wr + g) * FS + 8 * ks + tig + 4];
            pa[3] = Ps[(wr + g + 8) * FS + 8 * ks + tig + 4];
#pragma unroll
            for (int ni = 0; ni < 8; ni++) {
                unsigned b0 = Vs[(8 * ks + tig) * FS + 8 * ni + g];
                unsigned b1 = Vs[(8 * ks + tig + 4) * FS + 8 * ni + g];
                mma_tf32(o[ni], pa, b0, b1);
            }
        }
        __syncthreads();
    }

    const float i0 = 1.0f / l0, i1 = 1.0f / l1;
    const int grow = qt * 64 + wr;
#pragma unroll
    for (int ni = 0; ni < 8; ni++) {
        const int col = 8 * ni + 2 * tig;
        float2 r0 = make_float2(f2tff(o[ni][0] * i0), f2tff(o[ni][1] * i0));
        float2 r1 = make_float2(f2tff(o[ni][2] * i1), f2tff(o[ni][3] * i1));
        *(float2*)&g_ctx[base + (size_t)(grow + g) * E_DIM + col] = r0;
        *(float2*)&g_ctx[base + (size_t)(grow + g + 8) * E_DIM + col] = r1;
    }
}

// ---------------------------------------------------------------------------

extern "C" void kernel_launch(void* const* d_in, const int* in_sizes, int n_in,
                              void* d_out, int out_size)
{
    const float* x  = (const float*)d_in[0];
    const float* qw = (const float*)d_in[1];
    const float* qb = (const float*)d_in[2];
    const float* kw = (const float*)d_in[3];
    const float* kb = (const float*)d_in[4];
    const float* vw = (const float*)d_in[5];
    const float* vb = (const float*)d_in[6];
    const float* ow = (const float*)d_in[7];
    const float* ob = (const float*)d_in[8];
    float* out = (float*)d_out;

    const int gemm_smem  = 2 * 2 * GSTG * (int)sizeof(unsigned);      // 73728
    const int flash_smem = (2 * FSTG + 64 * FS) * (int)sizeof(unsigned); // 87040
    cudaFuncSetAttribute(k_gemm_qkv, cudaFuncAttributeMaxDynamicSharedMemorySize, gemm_smem);
    cudaFuncSetAttribute(k_gemm_out, cudaFuncAttributeMaxDynamicSharedMemorySize, gemm_smem);
    cudaFuncSetAttribute(k_flash,    cudaFuncAttributeMaxDynamicSharedMemorySize, flash_smem);

    k_prep<<<(unsigned)((XN + 4 * WN) / 4 / 256), 256>>>(x, qw, kw, vw, ow);

    dim3 gq(E_DIM / 128, MTOK / 128, 3);
    k_gemm_qkv<<<gq, 256, gemm_smem>>>(qb, kb, vb);

    dim3 gf(SEQ / 64, NH, 2);
    k_flash<<<gf, 128, flash_smem>>>();

    dim3 go(E_DIM / 128, MTOK / 128, 1);
    k_gemm_out<<<go, 256, gemm_smem>>>(ob, out);
}

// round 6
// speedup vs baseline: 1.3036x; 1.3036x over previous
#include <cuda_runtime.h>

#define E_DIM 1024
#define SEQ   2048
#define NH    16
#define HD    64
#define MTOK  4096
#define ATT_SCALE 0.125f
#define XN ((size_t)MTOK * E_DIM)
#define WN ((size_t)E_DIM * E_DIM)

__device__ float g_q[XN];
__device__ float g_k[XN];
__device__ float g_vT[XN];     // [B*H][HD][SEQ]
__device__ float g_ctx[XN];
__device__ float g_x[XN];
__device__ float g_wq[WN];
__device__ float g_wk[WN];
__device__ float g_wv[WN];
__device__ float g_wo[WN];

__device__ __forceinline__ unsigned f2tf(float x) {
    unsigned r;
    asm("cvt.rna.tf32.f32 %0, %1;" : "=r"(r) : "f"(x));
    return r;
}
__device__ __forceinline__ float f2tff(float x) {
    return __uint_as_float(f2tf(x));
}

__device__ __forceinline__ void mma_tf32(float* c, const unsigned* a,
                                         unsigned b0, unsigned b1) {
    asm volatile(
        "mma.sync.aligned.m16n8k8.row.col.f32.tf32.tf32.f32 "
        "{%0,%1,%2,%3}, {%4,%5,%6,%7}, {%8,%9}, {%0,%1,%2,%3};\n"
        : "+f"(c[0]), "+f"(c[1]), "+f"(c[2]), "+f"(c[3])
        : "r"(a[0]), "r"(a[1]), "r"(a[2]), "r"(a[3]), "r"(b0), "r"(b1));
}

__device__ __forceinline__ unsigned sptr(const void* p) {
    return (unsigned)__cvta_generic_to_shared(p);
}
__device__ __forceinline__ void cp16(unsigned d, const float* s) {
    asm volatile("cp.async.cg.shared.global [%0], [%1], 16;\n" :: "r"(d), "l"(s));
}
__device__ __forceinline__ void cp_commit() {
    asm volatile("cp.async.commit_group;\n");
}
template <int N>
__device__ __forceinline__ void cp_wait() {
    asm volatile("cp.async.wait_group %0;\n" :: "n"(N));
}

// ---------------------------------------------------------------------------
// Prep: round x + 4 weight matrices to rn-tf32 once.
// ---------------------------------------------------------------------------
__global__ void __launch_bounds__(256)
k_prep(const float* __restrict__ x,
       const float* __restrict__ wq, const float* __restrict__ wk,
       const float* __restrict__ wv, const float* __restrict__ wo)
{
    size_t i = ((size_t)blockIdx.x * 256 + threadIdx.x) * 4;
    const float* s; float* d; size_t off;
    if (i < XN)               { s = x;  d = g_x;  off = i; }
    else if (i < XN + WN)     { s = wq; d = g_wq; off = i - XN; }
    else if (i < XN + 2 * WN) { s = wk; d = g_wk; off = i - XN - WN; }
    else if (i < XN + 3 * WN) { s = wv; d = g_wv; off = i - XN - 2 * WN; }
    else                      { s = wo; d = g_wo; off = i - XN - 3 * WN; }
    float4 v = *(const float4*)(s + off);
    *(float4*)(d + off) =
        make_float4(f2tff(v.x), f2tff(v.y), f2tff(v.z), f2tff(v.w));
}

// ---------------------------------------------------------------------------
// tf32 GEMM: C = A[M,K] * W[N,K]^T + bias. Tile 128x128x16, 4-stage cp.async.
// 8 warps (4x2): warp = 32 rows x 64 cols. MODE: 0 plain, 1 tf32-round, 2 V^T.
// ---------------------------------------------------------------------------
#define KC  16
#define AST 20
#define GST (128 * AST)          // words, one array, one stage

template <int MODE>
__device__ __forceinline__ void gemm_body(const float* __restrict__ A,
                                          const float* __restrict__ W,
                                          const float* __restrict__ bias,
                                          float* __restrict__ C,
                                          unsigned* sm)
{
    const int tid  = threadIdx.x;
    const int lane = tid & 31, warp = tid >> 5;
    const int g = lane >> 2, tig = lane & 3;
    const int m0 = (warp >> 1) * 32;
    const int n0 = (warp & 1) * 64;
    const int row0 = blockIdx.y * 128;
    const int col0 = blockIdx.x * 128;

    const int lrow = tid >> 1;
    const int lcb  = (tid & 1) * 8;
    const float* Ag = A + (size_t)(row0 + lrow) * E_DIM + lcb;
    const float* Wg = W + (size_t)(col0 + lrow) * E_DIM + lcb;
    const unsigned dA0 = sptr(sm + lrow * AST + lcb);
    const unsigned dW0 = dA0 + GST * 4;
    const unsigned stageB = 2 * GST * 4;

    float acc[2][8][4];
#pragma unroll
    for (int mi = 0; mi < 2; mi++)
#pragma unroll
        for (int ni = 0; ni < 8; ni++)
#pragma unroll
            for (int j = 0; j < 4; j++) acc[mi][ni][j] = 0.f;

    // prologue: stages 0..2
#pragma unroll
    for (int s = 0; s < 3; s++) {
        const int ko = s * KC;
        cp16(dA0 + s * stageB,      Ag + ko);
        cp16(dA0 + s * stageB + 16, Ag + ko + 4);
        cp16(dW0 + s * stageB,      Wg + ko);
        cp16(dW0 + s * stageB + 16, Wg + ko + 4);
        cp_commit();
    }

    const int NKT = E_DIM / KC;   // 64
    for (int kt = 0; kt < NKT; kt++) {
        cp_wait<2>();
        __syncthreads();
        if (kt + 3 < NKT) {
            const unsigned sb = ((kt + 3) & 3) * stageB;
            const int ko = (kt + 3) * KC;
            cp16(dA0 + sb,      Ag + ko);
            cp16(dA0 + sb + 16, Ag + ko + 4);
            cp16(dW0 + sb,      Wg + ko);
            cp16(dW0 + sb + 16, Wg + ko + 4);
        }
        cp_commit();

        const unsigned* As = sm + (kt & 3) * 2 * GST;
        const unsigned* Ws = As + GST;
#pragma unroll
        for (int kk = 0; kk < KC; kk += 8) {
            unsigned a[2][4], bf[8][2];
#pragma unroll
            for (int mi = 0; mi < 2; mi++) {
                const int row = m0 + mi * 16;
                a[mi][0] = As[(row + g) * AST + kk + tig];
                a[mi][1] = As[(row + g + 8) * AST + kk + tig];
                a[mi][2] = As[(row + g) * AST + kk + tig + 4];
                a[mi][3] = As[(row + g + 8) * AST + kk + tig + 4];
            }
#pragma unroll
            for (int ni = 0; ni < 8; ni++) {
                const int col = n0 + ni * 8;
                bf[ni][0] = Ws[(col + g) * AST + kk + tig];
                bf[ni][1] = Ws[(col + g) * AST + kk + tig + 4];
            }
#pragma unroll
            for (int mi = 0; mi < 2; mi++)
#pragma unroll
                for (int ni = 0; ni < 8; ni++)
                    mma_tf32(acc[mi][ni], a[mi], bf[ni][0], bf[ni][1]);
        }
    }

#pragma unroll
    for (int mi = 0; mi < 2; mi++) {
#pragma unroll
        for (int ni = 0; ni < 8; ni++) {
            const int row = row0 + m0 + mi * 16;
            const int col = col0 + n0 + ni * 8 + 2 * tig;
            const float bx = bias[col], by = bias[col + 1];
            if (MODE == 2) {
                // transposed store: g_vT[(b*NH+h)*HD + dim][token]
#pragma unroll
                for (int rr = 0; rr < 2; rr++) {
                    const int r = row + g + rr * 8;
                    const int b = r >> 11, s = r & 2047;
                    const float v0 = f2tff(acc[mi][ni][2 * rr + 0] + bx);
                    const float v1 = f2tff(acc[mi][ni][2 * rr + 1] + by);
                    const size_t d0 = ((size_t)(b * NH + (col >> 6)) * HD + (col & 63)) * SEQ + s;
                    C[d0] = v0;
                    C[d0 + SEQ] = v1;   // col+1 same head (col%64 < 63 always here)
                }
            } else {
                float2 r0, r1;
                if (MODE == 1) {
                    r0 = make_float2(f2tff(acc[mi][ni][0] + bx), f2tff(acc[mi][ni][1] + by));
                    r1 = make_float2(f2tff(acc[mi][ni][2] + bx), f2tff(acc[mi][ni][3] + by));
                } else {
                    r0 = make_float2(acc[mi][ni][0] + bx, acc[mi][ni][1] + by);
                    r1 = make_float2(acc[mi][ni][2] + bx, acc[mi][ni][3] + by);
                }
                *(float2*)&C[(size_t)(row + g) * E_DIM + col] = r0;
                *(float2*)&C[(size_t)(row + g + 8) * E_DIM + col] = r1;
            }
        }
    }
}

__global__ void __launch_bounds__(256, 2)
k_gemm_qkv(const float* __restrict__ bq, const float* __restrict__ bk,
           const float* __restrict__ bv)
{
    extern __shared__ unsigned dynsm[];
    if (blockIdx.z == 0)      gemm_body<1>(g_x, g_wq, bq, g_q,  dynsm);
    else if (blockIdx.z == 1) gemm_body<1>(g_x, g_wk, bk, g_k,  dynsm);
    else                      gemm_body<2>(g_x, g_wv, bv, g_vT, dynsm);
}

__global__ void __launch_bounds__(256, 2)
k_gemm_out(const float* __restrict__ bo, float* __restrict__ Cout)
{
    extern __shared__ unsigned dynsm[];
    gemm_body<0>(g_ctx, g_wo, bo, Cout, dynsm);
}

// ---------------------------------------------------------------------------
// Flash attention tf32. CTA = (b,h,128-query tile), 256 thr = 8 warps,
// warp owns 16 query rows. K + V^T tiles (64 tokens) 2-stage cp.async.
// ---------------------------------------------------------------------------
#define FS   68
#define FSTG (2 * 64 * FS)      // K + VT, one stage (words)

__global__ void __launch_bounds__(256, 2) k_flash()
{
    extern __shared__ unsigned sm[];
    unsigned* Ps = sm + 2 * FSTG;   // 128 x FS (Q staging, then P)

    const int tid  = threadIdx.x;
    const int lane = tid & 31, warp = tid >> 5;
    const int g = lane >> 2, tig = lane & 3;
    const int qt = blockIdx.x, h = blockIdx.y, b = blockIdx.z;
    const size_t base   = (size_t)b * SEQ * E_DIM + (size_t)h * HD;
    const size_t vtbase = (size_t)(b * NH + h) * HD * SEQ;
    const int wr = warp * 16;

    const int lr = tid >> 2;            // 0..63
    const int c  = (tid & 3) * 16;      // 0,16,32,48 (floats)
    const float* Kg = g_k  + base   + (size_t)lr * E_DIM + c;
    const float* Vg = g_vT + vtbase + (size_t)lr * SEQ   + c;
    const unsigned dK0 = sptr(sm + lr * FS + c);
    const unsigned dV0 = dK0 + 64 * FS * 4;

    // prologue: stage 0 = kt 0
#pragma unroll
    for (int j = 0; j < 4; j++) {
        cp16(dK0 + 16 * j, Kg + 4 * j);
        cp16(dV0 + 16 * j, Vg + 4 * j);
    }
    cp_commit();

    // stage Q (128 x 64, pre-rounded) into Ps, pull frags
    for (int i = tid; i < 128 * 16; i += 256) {
        const int rr = i >> 4, c4 = (i & 15) << 2;
        *(float4*)&Ps[rr * FS + c4] =
            *(const float4*)&g_q[base + (size_t)(qt * 128 + rr) * E_DIM + c4];
    }
    __syncthreads();

    unsigned qa[8][4];
#pragma unroll
    for (int ks = 0; ks < 8; ks++) {
        qa[ks][0] = Ps[(wr + g) * FS + 8 * ks + tig];
        qa[ks][1] = Ps[(wr + g + 8) * FS + 8 * ks + tig];
        qa[ks][2] = Ps[(wr + g) * FS + 8 * ks + tig + 4];
        qa[ks][3] = Ps[(wr + g + 8) * FS + 8 * ks + tig + 4];
    }

    float o[8][4];
#pragma unroll
    for (int ni = 0; ni < 8; ni++)
#pragma unroll
        for (int j = 0; j < 4; j++) o[ni][j] = 0.f;
    float m0 = -3.0e38f, m1 = -3.0e38f, l0 = 0.f, l1 = 0.f;

    const int NT = SEQ / 64;
    for (int kt = 0; kt < NT; kt++) {
        __syncthreads();                       // prev reads of buf^1 done
        if (kt + 1 < NT) {
            const unsigned dd = ((kt + 1) & 1) * FSTG * 4;
            const float* kp = Kg + (size_t)(kt + 1) * 64 * E_DIM;
            const float* vp = Vg + (kt + 1) * 64;
#pragma unroll
            for (int j = 0; j < 4; j++) {
                cp16(dK0 + dd + 16 * j, kp + 4 * j);
                cp16(dV0 + dd + 16 * j, vp + 4 * j);
            }
        }
        cp_commit();
        cp_wait<1>();
        __syncthreads();                       // stage kt visible to all

        const unsigned* Ks = sm + (kt & 1) * FSTG;
        const unsigned* Vs = Ks + 64 * FS;

        // S = Q K^T
        float s[8][4];
#pragma unroll
        for (int ni = 0; ni < 8; ni++)
#pragma unroll
            for (int j = 0; j < 4; j++) s[ni][j] = 0.f;
#pragma unroll
        for (int ks = 0; ks < 8; ks++) {
#pragma unroll
            for (int ni = 0; ni < 8; ni++) {
                unsigned b0 = Ks[(8 * ni + g) * FS + 8 * ks + tig];
                unsigned b1 = Ks[(8 * ni + g) * FS + 8 * ks + tig + 4];
                mma_tf32(s[ni], qa[ks], b0, b1);
            }
        }

        // online softmax
        float mx0 = -3.0e38f, mx1 = -3.0e38f;
#pragma unroll
        for (int ni = 0; ni < 8; ni++) {
            s[ni][0] *= ATT_SCALE; s[ni][1] *= ATT_SCALE;
            s[ni][2] *= ATT_SCALE; s[ni][3] *= ATT_SCALE;
            mx0 = fmaxf(mx0, fmaxf(s[ni][0], s[ni][1]));
            mx1 = fmaxf(mx1, fmaxf(s[ni][2], s[ni][3]));
        }
        mx0 = fmaxf(mx0, __shfl_xor_sync(0xffffffffu, mx0, 1));
        mx0 = fmaxf(mx0, __shfl_xor_sync(0xffffffffu, mx0, 2));
        mx1 = fmaxf(mx1, __shfl_xor_sync(0xffffffffu, mx1, 1));
        mx1 = fmaxf(mx1, __shfl_xor_sync(0xffffffffu, mx1, 2));
        const float mn0 = fmaxf(m0, mx0), mn1 = fmaxf(m1, mx1);
        const float al0 = __expf(m0 - mn0), al1 = __expf(m1 - mn1);
        float s0 = 0.f, s1 = 0.f;
#pragma unroll
        for (int ni = 0; ni < 8; ni++) {
            float p0 = __expf(s[ni][0] - mn0);
            float p1 = __expf(s[ni][1] - mn0);
            float p2 = __expf(s[ni][2] - mn1);
            float p3 = __expf(s[ni][3] - mn1);
            s0 += p0 + p1; s1 += p2 + p3;
            *(uint2*)&Ps[(wr + g) * FS + 8 * ni + 2 * tig] =
                make_uint2(f2tf(p0), f2tf(p1));
            *(uint2*)&Ps[(wr + g + 8) * FS + 8 * ni + 2 * tig] =
                make_uint2(f2tf(p2), f2tf(p3));
        }
        s0 += __shfl_xor_sync(0xffffffffu, s0, 1);
        s0 += __shfl_xor_sync(0xffffffffu, s0, 2);
        s1 += __shfl_xor_sync(0xffffffffu, s1, 1);
        s1 += __shfl_xor_sync(0xffffffffu, s1, 2);
        l0 = l0 * al0 + s0;
        l1 = l1 * al1 + s1;
        m0 = mn0; m1 = mn1;
#pragma unroll
        for (int ni = 0; ni < 8; ni++) {
            o[ni][0] *= al0; o[ni][1] *= al0;
            o[ni][2] *= al1; o[ni][3] *= al1;
        }
        __syncwarp();

        // O += P V : B-frags from V^T (row pattern, conflict-free)
#pragma unroll
        for (int ks = 0; ks < 8; ks++) {
            unsigned pa[4];
            pa[0] = Ps[(wr + g) * FS + 8 * ks + tig];
            pa[1] = Ps[(wr + g + 8) * FS + 8 * ks + tig];
            pa[2] = Ps[(wr + g) * FS + 8 * ks + tig + 4];
            pa[3] = Ps[(wr + g + 8) * FS + 8 * ks + tig + 4];
#pragma unroll
            for (int ni = 0; ni < 8; ni++) {
                unsigned b0 = Vs[(8 * ni + g) * FS + 8 * ks + tig];
                unsigned b1 = Vs[(8 * ni + g) * FS + 8 * ks + tig + 4];
                mma_tf32(o[ni], pa, b0, b1);
            }
        }
    }

    const float i0 = 1.0f / l0, i1 = 1.0f / l1;
    const int grow = qt * 128 + wr;
#pragma unroll
    for (int ni = 0; ni < 8; ni++) {
        const int col = 8 * ni + 2 * tig;
        float2 r0 = make_float2(f2tff(o[ni][0] * i0), f2tff(o[ni][1] * i0));
        float2 r1 = make_float2(f2tff(o[ni][2] * i1), f2tff(o[ni][3] * i1));
        *(float2*)&g_ctx[base + (size_t)(grow + g) * E_DIM + col] = r0;
        *(float2*)&g_ctx[base + (size_t)(grow + g + 8) * E_DIM + col] = r1;
    }
}

// ---------------------------------------------------------------------------

extern "C" void kernel_launch(void* const* d_in, const int* in_sizes, int n_in,
                              void* d_out, int out_size)
{
    const float* x  = (const float*)d_in[0];
    const float* qw = (const float*)d_in[1];
    const float* qb = (const float*)d_in[2];
    const float* kw = (const float*)d_in[3];
    const float* kb = (const float*)d_in[4];
    const float* vw = (const float*)d_in[5];
    const float* vb = (const float*)d_in[6];
    const float* ow = (const float*)d_in[7];
    const float* ob = (const float*)d_in[8];
    float* out = (float*)d_out;

    const int gemm_smem  = 4 * 2 * GST * (int)sizeof(unsigned);            // 81920
    const int flash_smem = (2 * FSTG + 128 * FS) * (int)sizeof(unsigned);  // 104448
    cudaFuncSetAttribute(k_gemm_qkv, cudaFuncAttributeMaxDynamicSharedMemorySize, gemm_smem);
    cudaFuncSetAttribute(k_gemm_out, cudaFuncAttributeMaxDynamicSharedMemorySize, gemm_smem);
    cudaFuncSetAttribute(k_flash,    cudaFuncAttributeMaxDynamicSharedMemorySize, flash_smem);

    k_prep<<<(unsigned)((XN + 4 * WN) / 4 / 256), 256>>>(x, qw, kw, vw, ow);

    dim3 gq(E_DIM / 128, MTOK / 128, 3);
    k_gemm_qkv<<<gq, 256, gemm_smem>>>(qb, kb, vb);

    dim3 gf(SEQ / 128, NH, 2);
    k_flash<<<gf, 256, flash_smem>>>();

    dim3 go(E_DIM / 128, MTOK / 128, 1);
    k_gemm_out<<<go, 256, gemm_smem>>>(ob, out);
}